// round 9
// baseline (speedup 1.0000x reference)
#include <cuda_runtime.h>
#include <float.h>

// Shapes (fixed): network_mesh (4,3,32,32) f32 = d_in[0]; pc (4,3,4096) f32 = d_in[1].
// Output: scalar f32 = mean over 4*4096 nearest-refined-mesh squared distances.
#define B_       4
#define H_       32
#define W_       32
#define FAC_     3
#define OH_      94          // (32-1)*3+1
#define OW_      94
#define NMESH_   (OH_ * OW_) // 8836
#define M_       4096
#define SLICES_  55          // grid = 4*2*55 = 440 <= 444 = one full wave at 3 CTAs/SM
#define SLICE_   162         // EVEN; 54*162=8748, last slice = 88 (also even)
#define PAIRS_   (SLICE_ / 2)
#define THREADS_ 256
#define RPT_     8           // pc POINTS per thread (8 points)
#define CHUNKS_  2           // 4096 / (256 thr * 8 pts)
#define R1BLOCKS_ 64

// Allocation-free scratch.
__device__ float g_partial[SLICES_ * B_ * M_];   // per-slice per-point minima (incl |p|^2)
__device__ float g_sums[R1BLOCKS_];

union df2 { unsigned long long u; float2 f; };

__device__ __forceinline__ unsigned long long pack2(float lo, float hi) {
    df2 t; t.f = make_float2(lo, hi); return t.u;
}

// Packed dual-FMA (Blackwell f32x2 path). No packed f32 min exists in PTX.
__device__ __forceinline__ unsigned long long fma2(unsigned long long a,
                                                   unsigned long long b,
                                                   unsigned long long c) {
    unsigned long long r;
    asm("fma.rn.f32x2 %0, %1, %2, %3;" : "=l"(r) : "l"(a), "l"(b), "l"(c));
    return r;
}

// ---------------------------------------------------------------------------
// Kernel 1: fused refine + nearest-point partial minima.
// Lane packing: the two f32x2 lanes carry TWO MESH POINTS against one pc point
// (pc coords duplicated in registers at setup). smem holds mesh pairs
// {x0,x1}{y0,y1} / {z0,z1}{w0,w1} -> ONE LDS.128 per mesh point (halved).
// grid = (B, CHUNKS, SLICES) = (4,2,55) = 440 blocks: single wave, 3 CTAs/SM.
// ---------------------------------------------------------------------------
__global__ __launch_bounds__(THREADS_, 3)
void dist_kernel(const float* __restrict__ mesh, const float* __restrict__ pc) {
    __shared__ ulonglong2 sa[PAIRS_];   // {x0,x1},{y0,y1}
    __shared__ ulonglong2 sb[PAIRS_];   // {z0,z1},{w0,w1}   w = |m|^2

    const int b     = blockIdx.x;
    const int chunk = blockIdx.y;
    const int s     = blockIdx.z;

    const int base = s * SLICE_;
    const int cnt  = (base + SLICE_ <= NMESH_) ? SLICE_ : (NMESH_ - base);  // even

    // --- Inline bilinear refine (align_corners, factor 3) for this slice ---
    const float* __restrict__ m0 = mesh + (b * 3 + 0) * H_ * W_;
    const float* __restrict__ m1 = mesh + (b * 3 + 1) * H_ * W_;
    const float* __restrict__ m2 = mesh + (b * 3 + 2) * H_ * W_;

    if (threadIdx.x < cnt) {
        int i = threadIdx.x;                 // SLICE_ <= THREADS_, one pass
        int idx = base + i;
        int r = idx / OW_;
        int c = idx - r * OW_;
        int y0 = r / FAC_; if (y0 > H_ - 2) y0 = H_ - 2;
        int x0 = c / FAC_; if (x0 > W_ - 2) x0 = W_ - 2;
        float wy = (float)r / (float)FAC_ - (float)y0;
        float wx = (float)c / (float)FAC_ - (float)x0;
        int o00 = y0 * W_ + x0, o01 = o00 + 1, o10 = o00 + W_, o11 = o10 + 1;

        float t0 = m0[o00] * (1.0f - wx) + m0[o01] * wx;
        float u0 = m0[o10] * (1.0f - wx) + m0[o11] * wx;
        float v0 = t0 * (1.0f - wy) + u0 * wy;

        float t1 = m1[o00] * (1.0f - wx) + m1[o01] * wx;
        float u1 = m1[o10] * (1.0f - wx) + m1[o11] * wx;
        float v1 = t1 * (1.0f - wy) + u1 * wy;

        float t2 = m2[o00] * (1.0f - wx) + m2[o01] * wx;
        float u2 = m2[o10] * (1.0f - wx) + m2[o11] * wx;
        float v2 = t2 * (1.0f - wy) + u2 * wy;

        float w = fmaf(v0, v0, fmaf(v1, v1, v2 * v2));

        // Scatter into pair layout: fa[4*jp + {0,1}]=x, fa[4*jp + {2,3}]=y, etc.
        int jp   = i >> 1;
        int lane = i & 1;
        float* fa = (float*)sa;
        float* fb = (float*)sb;
        fa[4 * jp + lane]     = v0;
        fa[4 * jp + 2 + lane] = v1;
        fb[4 * jp + lane]     = v2;
        fb[4 * jp + 2 + lane] = w;
    }
    __syncthreads();

    // --- Load this thread's pc points; duplicate coords into packed regs ---
    const float* __restrict__ px = pc + (b * 3 + 0) * M_;
    const float* __restrict__ py = pc + (b * 3 + 1) * M_;
    const float* __restrict__ pz = pc + (b * 3 + 2) * M_;

    const int q0 = chunk * (THREADS_ * RPT_) + threadIdx.x;   // pc point index

    unsigned long long ax2[RPT_], ay2[RPT_], az2[RPT_];
    float b0[RPT_], b1[RPT_];
#pragma unroll
    for (int r = 0; r < RPT_; r++) {
        int q = q0 + r * THREADS_;
        float x = px[q], y = py[q], z = pz[q];
        ax2[r] = pack2(-2.0f * x, -2.0f * x);
        ay2[r] = pack2(-2.0f * y, -2.0f * y);
        az2[r] = pack2(-2.0f * z, -2.0f * z);
        b0[r] = FLT_MAX;
        b1[r] = FLT_MAX;
    }

    // --- Hot loop over mesh PAIRS: one packed FMA chain = 2 mesh distances ---
    const int pairs = cnt >> 1;
#pragma unroll 2
    for (int jp = 0; jp < pairs; jp++) {
        ulonglong2 A  = sa[jp];   // broadcast LDS.128: {x0,x1},{y0,y1}
        ulonglong2 Bv = sb[jp];   // {z0,z1},{w0,w1}
#pragma unroll
        for (int r = 0; r < RPT_; r++) {
            df2 t;
            t.u = fma2(A.x, ax2[r], fma2(A.y, ay2[r], fma2(Bv.x, az2[r], Bv.y)));
            b0[r] = fminf(b0[r], t.f.x);   // mesh point 2*jp
            b1[r] = fminf(b1[r], t.f.y);   // mesh point 2*jp+1
        }
    }

    // --- Epilogue: cross-lane min, recompute |p|^2 (L2-hot reload), emit ---
#pragma unroll
    for (int r = 0; r < RPT_; r++) {
        int q = q0 + r * THREADS_;
        float x = px[q], y = py[q], z = pz[q];
        float pp = fmaf(x, x, fmaf(y, y, z * z));
        g_partial[(s * B_ + b) * M_ + q] = fminf(b0[r], b1[r]) + pp;
    }
}

// ---------------------------------------------------------------------------
// Kernel 2: per-point min across slices + per-block deterministic tree sum.
// ---------------------------------------------------------------------------
__global__ __launch_bounds__(THREADS_)
void reduce1_kernel() {
    __shared__ float red[THREADS_];
    const int i = blockIdx.x * THREADS_ + threadIdx.x;   // i < 16384
    float v = g_partial[i];
#pragma unroll
    for (int s = 1; s < SLICES_; s++)
        v = fminf(v, g_partial[s * (B_ * M_) + i]);
    red[threadIdx.x] = v;
    __syncthreads();
#pragma unroll
    for (int off = THREADS_ / 2; off > 0; off >>= 1) {
        if (threadIdx.x < off) red[threadIdx.x] += red[threadIdx.x + off];
        __syncthreads();
    }
    if (threadIdx.x == 0) g_sums[blockIdx.x] = red[0];
}

// ---------------------------------------------------------------------------
// Kernel 3: final deterministic sum of 64 partials + mean.
// ---------------------------------------------------------------------------
__global__ void reduce2_kernel(float* __restrict__ out) {
    __shared__ float red[R1BLOCKS_];
    red[threadIdx.x] = g_sums[threadIdx.x];
    __syncthreads();
#pragma unroll
    for (int off = R1BLOCKS_ / 2; off > 0; off >>= 1) {
        if (threadIdx.x < off) red[threadIdx.x] += red[threadIdx.x + off];
        __syncthreads();
    }
    if (threadIdx.x == 0) out[0] = red[0] / (float)(B_ * M_);
}

// ---------------------------------------------------------------------------
extern "C" void kernel_launch(void* const* d_in, const int* in_sizes, int n_in,
                              void* d_out, int out_size) {
    const float* mesh = (const float*)d_in[0];
    const float* pc   = (const float*)d_in[1];
    float* out = (float*)d_out;

    dim3 grid(B_, CHUNKS_, SLICES_);
    dist_kernel<<<grid, THREADS_>>>(mesh, pc);
    reduce1_kernel<<<R1BLOCKS_, THREADS_>>>();
    reduce2_kernel<<<1, R1BLOCKS_>>>(out);
}

// round 10
// speedup vs baseline: 1.0501x; 1.0501x over previous
#include <cuda_runtime.h>
#include <float.h>

// Shapes (fixed): network_mesh (4,3,32,32) f32 = d_in[0]; pc (4,3,4096) f32 = d_in[1].
// Output: scalar f32 = mean over 4*4096 nearest-refined-mesh squared distances.
#define B_       4
#define H_       32
#define W_       32
#define FAC_     3
#define OH_      94          // (32-1)*3+1
#define OW_      94
#define NMESH_   (OH_ * OW_) // 8836
#define M_       4096
#define SLICES_  37          // grid = 4*4*37 = 592 = exactly one wave at 4 CTAs/SM
#define SLICE_   240         // EVEN; 36*240=8640, last slice = 196 (even)
#define PAIRS_   (SLICE_ / 2)
#define THREADS_ 256
#define RPT_     4           // pc POINTS per thread
#define CHUNKS_  4           // 4096 / (256 thr * 4 pts)
#define RBLOCKS_ 64

// Allocation-free scratch.
__device__ float g_partial[SLICES_ * B_ * M_];   // per-slice per-point minima (incl |p|^2)
__device__ float g_sums[RBLOCKS_];
__device__ unsigned int g_ticket;                 // zero-init; last block resets it

union df2 { unsigned long long u; float2 f; };

__device__ __forceinline__ unsigned long long pack2(float lo, float hi) {
    df2 t; t.f = make_float2(lo, hi); return t.u;
}

// Packed dual-FMA (Blackwell f32x2 path). No packed f32 min exists in PTX.
__device__ __forceinline__ unsigned long long fma2(unsigned long long a,
                                                   unsigned long long b,
                                                   unsigned long long c) {
    unsigned long long r;
    asm("fma.rn.f32x2 %0, %1, %2, %3;" : "=l"(r) : "l"(a), "l"(b), "l"(c));
    return r;
}

// ---------------------------------------------------------------------------
// Kernel 1: fused refine + nearest-point partial minima.
// Lanes carry TWO MESH POINTS vs one pc point (pc coords duplicated in regs):
// smem mesh pairs {x0,x1}{y0,y1} / {z0,z1}{w0,w1} -> one LDS.128 per mesh pt.
// grid = (4,4,37) = 592 blocks: single wave at 4 CTAs/SM (32 warps/SM).
// RPT=4 keeps live state ~55 regs so the 64-reg cap does not spill.
// ---------------------------------------------------------------------------
__global__ __launch_bounds__(THREADS_, 4)
void dist_kernel(const float* __restrict__ mesh, const float* __restrict__ pc) {
    __shared__ ulonglong2 sa[PAIRS_];   // {x0,x1},{y0,y1}
    __shared__ ulonglong2 sb[PAIRS_];   // {z0,z1},{w0,w1}   w = |m|^2

    const int b     = blockIdx.x;
    const int chunk = blockIdx.y;
    const int s     = blockIdx.z;

    const int base = s * SLICE_;
    const int cnt  = (base + SLICE_ <= NMESH_) ? SLICE_ : (NMESH_ - base);  // even

    // --- Inline bilinear refine (align_corners, factor 3) for this slice ---
    const float* __restrict__ m0 = mesh + (b * 3 + 0) * H_ * W_;
    const float* __restrict__ m1 = mesh + (b * 3 + 1) * H_ * W_;
    const float* __restrict__ m2 = mesh + (b * 3 + 2) * H_ * W_;

    if (threadIdx.x < cnt) {
        int i = threadIdx.x;                 // SLICE_ <= THREADS_, one pass
        int idx = base + i;
        int r = idx / OW_;
        int c = idx - r * OW_;
        int y0 = r / FAC_; if (y0 > H_ - 2) y0 = H_ - 2;
        int x0 = c / FAC_; if (x0 > W_ - 2) x0 = W_ - 2;
        float wy = (float)r / (float)FAC_ - (float)y0;
        float wx = (float)c / (float)FAC_ - (float)x0;
        int o00 = y0 * W_ + x0, o01 = o00 + 1, o10 = o00 + W_, o11 = o10 + 1;

        float t0 = m0[o00] * (1.0f - wx) + m0[o01] * wx;
        float u0 = m0[o10] * (1.0f - wx) + m0[o11] * wx;
        float v0 = t0 * (1.0f - wy) + u0 * wy;

        float t1 = m1[o00] * (1.0f - wx) + m1[o01] * wx;
        float u1 = m1[o10] * (1.0f - wx) + m1[o11] * wx;
        float v1 = t1 * (1.0f - wy) + u1 * wy;

        float t2 = m2[o00] * (1.0f - wx) + m2[o01] * wx;
        float u2 = m2[o10] * (1.0f - wx) + m2[o11] * wx;
        float v2 = t2 * (1.0f - wy) + u2 * wy;

        float w = fmaf(v0, v0, fmaf(v1, v1, v2 * v2));

        // Scatter into pair layout.
        int jp   = i >> 1;
        int lane = i & 1;
        float* fa = (float*)sa;
        float* fb = (float*)sb;
        fa[4 * jp + lane]     = v0;
        fa[4 * jp + 2 + lane] = v1;
        fb[4 * jp + lane]     = v2;
        fb[4 * jp + 2 + lane] = w;
    }
    __syncthreads();

    // --- Load this thread's pc points; duplicate coords into packed regs ---
    const float* __restrict__ px = pc + (b * 3 + 0) * M_;
    const float* __restrict__ py = pc + (b * 3 + 1) * M_;
    const float* __restrict__ pz = pc + (b * 3 + 2) * M_;

    const int q0 = chunk * (THREADS_ * RPT_) + threadIdx.x;   // pc point index

    unsigned long long ax2[RPT_], ay2[RPT_], az2[RPT_];
    float b0[RPT_], b1[RPT_];
#pragma unroll
    for (int r = 0; r < RPT_; r++) {
        int q = q0 + r * THREADS_;
        float x = px[q], y = py[q], z = pz[q];
        ax2[r] = pack2(-2.0f * x, -2.0f * x);
        ay2[r] = pack2(-2.0f * y, -2.0f * y);
        az2[r] = pack2(-2.0f * z, -2.0f * z);
        b0[r] = FLT_MAX;
        b1[r] = FLT_MAX;
    }

    // --- Hot loop over mesh PAIRS: one packed FMA chain = 2 mesh distances ---
    const int pairs = cnt >> 1;
#pragma unroll 2
    for (int jp = 0; jp < pairs; jp++) {
        ulonglong2 A  = sa[jp];   // broadcast LDS.128: {x0,x1},{y0,y1}
        ulonglong2 Bv = sb[jp];   // {z0,z1},{w0,w1}
#pragma unroll
        for (int r = 0; r < RPT_; r++) {
            df2 t;
            t.u = fma2(A.x, ax2[r], fma2(A.y, ay2[r], fma2(Bv.x, az2[r], Bv.y)));
            b0[r] = fminf(b0[r], t.f.x);
            b1[r] = fminf(b1[r], t.f.y);
        }
    }

    // --- Epilogue: cross-lane min, recompute |p|^2 (L2-hot reload), emit ---
#pragma unroll
    for (int r = 0; r < RPT_; r++) {
        int q = q0 + r * THREADS_;
        float x = px[q], y = py[q], z = pz[q];
        float pp = fmaf(x, x, fmaf(y, y, z * z));
        g_partial[(s * B_ + b) * M_ + q] = fminf(b0[r], b1[r]) + pp;
    }
}

// ---------------------------------------------------------------------------
// Kernel 2: fused reduce. 64 blocks; each thread min-folds its point across
// slices, block tree-sums; LAST block (atomic ticket) sums the 64 partials in
// fixed order and writes the mean. Counter self-resets -> graph-replayable,
// fully deterministic (all sums are fixed-order trees).
// ---------------------------------------------------------------------------
__global__ __launch_bounds__(THREADS_)
void reduce_kernel(float* __restrict__ out) {
    __shared__ float red[THREADS_];
    __shared__ unsigned int s_ticket;

    const int i = blockIdx.x * THREADS_ + threadIdx.x;   // i < 16384
    float v = g_partial[i];
#pragma unroll
    for (int s = 1; s < SLICES_; s++)
        v = fminf(v, g_partial[s * (B_ * M_) + i]);
    red[threadIdx.x] = v;
    __syncthreads();
#pragma unroll
    for (int off = THREADS_ / 2; off > 0; off >>= 1) {
        if (threadIdx.x < off) red[threadIdx.x] += red[threadIdx.x + off];
        __syncthreads();
    }
    if (threadIdx.x == 0) {
        g_sums[blockIdx.x] = red[0];
        __threadfence();
        s_ticket = atomicAdd(&g_ticket, 1u);
    }
    __syncthreads();

    if (s_ticket == RBLOCKS_ - 1) {          // last block to finish
        if (threadIdx.x < RBLOCKS_) red[threadIdx.x] = g_sums[threadIdx.x];
        __syncthreads();
#pragma unroll
        for (int off = RBLOCKS_ / 2; off > 0; off >>= 1) {
            if (threadIdx.x < off) red[threadIdx.x] += red[threadIdx.x + off];
            __syncthreads();
        }
        if (threadIdx.x == 0) {
            out[0] = red[0] / (float)(B_ * M_);
            g_ticket = 0;                     // reset for next graph replay
        }
    }
}

// ---------------------------------------------------------------------------
extern "C" void kernel_launch(void* const* d_in, const int* in_sizes, int n_in,
                              void* d_out, int out_size) {
    const float* mesh = (const float*)d_in[0];
    const float* pc   = (const float*)d_in[1];
    float* out = (float*)d_out;

    dim3 grid(B_, CHUNKS_, SLICES_);
    dist_kernel<<<grid, THREADS_>>>(mesh, pc);
    reduce_kernel<<<RBLOCKS_, THREADS_>>>(out);
}

// round 11
// speedup vs baseline: 1.1042x; 1.0515x over previous
#include <cuda_runtime.h>
#include <float.h>

// Shapes (fixed): network_mesh (4,3,32,32) f32 = d_in[0]; pc (4,3,4096) f32 = d_in[1].
// Output: scalar f32 = mean over 4*4096 nearest-refined-mesh squared distances.
#define B_       4
#define H_       32
#define W_       32
#define FAC_     3
#define OH_      94          // (32-1)*3+1
#define OW_      94
#define NMESH_   (OH_ * OW_) // 8836
#define M_       4096
#define SLICES_  37          // grid = 4*4*37 = 592 = exactly one wave at 4 CTAs/SM
#define SLICE_   240         // EVEN; 36*240=8640, last slice = 196 (even)
#define PAIRS_   (SLICE_ / 2)
#define THREADS_ 256
#define RPT_     4           // pc POINTS per thread
#define CHUNKS_  4           // 4096 / (256 thr * 4 pts)
#define RBLOCKS_ 64

// Allocation-free scratch.
// g_best holds ~enc(min dist) per point; 0 == "+infinity". The reduce kernel
// resets it to 0 after consuming it, so every graph replay sees the same state.
__device__ unsigned int g_best[B_ * M_];
__device__ float        g_sums[RBLOCKS_];
__device__ unsigned int g_ticket;            // zero-init; last block resets it

union df2 { unsigned long long u; float2 f; };

__device__ __forceinline__ unsigned long long pack2(float lo, float hi) {
    df2 t; t.f = make_float2(lo, hi); return t.u;
}

// Packed dual-FMA (Blackwell f32x2 path). No packed f32 min exists in PTX.
__device__ __forceinline__ unsigned long long fma2(unsigned long long a,
                                                   unsigned long long b,
                                                   unsigned long long c) {
    unsigned long long r;
    asm("fma.rn.f32x2 %0, %1, %2, %3;" : "=l"(r) : "l"(a), "l"(b), "l"(c));
    return r;
}

// Monotonic float->uint key: larger float <=> larger key (handles negatives).
__device__ __forceinline__ unsigned int enc_f32(float f) {
    unsigned int u = __float_as_uint(f);
    return u ^ ((u >> 31) ? 0xFFFFFFFFu : 0x80000000u);
}
__device__ __forceinline__ float dec_f32(unsigned int e) {
    unsigned int u = (e & 0x80000000u) ? (e ^ 0x80000000u) : ~e;
    return __uint_as_float(u);
}

// ---------------------------------------------------------------------------
// Kernel 1: fused refine + nearest-point partial minima -> atomicMax(~enc).
// Lanes carry TWO MESH POINTS vs one pc point (pc coords duplicated in regs):
// smem mesh pairs {x0,x1}{y0,y1} / {z0,z1}{w0,w1} -> one LDS.128 per mesh pt.
// grid = (4,4,37) = 592 blocks: single wave at 4 CTAs/SM (32 warps/SM).
// ---------------------------------------------------------------------------
__global__ __launch_bounds__(THREADS_, 4)
void dist_kernel(const float* __restrict__ mesh, const float* __restrict__ pc) {
    __shared__ ulonglong2 sa[PAIRS_];   // {x0,x1},{y0,y1}
    __shared__ ulonglong2 sb[PAIRS_];   // {z0,z1},{w0,w1}   w = |m|^2

    const int b     = blockIdx.x;
    const int chunk = blockIdx.y;
    const int s     = blockIdx.z;

    const int base = s * SLICE_;
    const int cnt  = (base + SLICE_ <= NMESH_) ? SLICE_ : (NMESH_ - base);  // even

    // --- Inline bilinear refine (align_corners, factor 3) for this slice ---
    const float* __restrict__ m0 = mesh + (b * 3 + 0) * H_ * W_;
    const float* __restrict__ m1 = mesh + (b * 3 + 1) * H_ * W_;
    const float* __restrict__ m2 = mesh + (b * 3 + 2) * H_ * W_;

    if (threadIdx.x < cnt) {
        int i = threadIdx.x;                 // SLICE_ <= THREADS_, one pass
        int idx = base + i;
        int r = idx / OW_;
        int c = idx - r * OW_;
        int y0 = r / FAC_; if (y0 > H_ - 2) y0 = H_ - 2;
        int x0 = c / FAC_; if (x0 > W_ - 2) x0 = W_ - 2;
        float wy = (float)r / (float)FAC_ - (float)y0;
        float wx = (float)c / (float)FAC_ - (float)x0;
        int o00 = y0 * W_ + x0, o01 = o00 + 1, o10 = o00 + W_, o11 = o10 + 1;

        float t0 = m0[o00] * (1.0f - wx) + m0[o01] * wx;
        float u0 = m0[o10] * (1.0f - wx) + m0[o11] * wx;
        float v0 = t0 * (1.0f - wy) + u0 * wy;

        float t1 = m1[o00] * (1.0f - wx) + m1[o01] * wx;
        float u1 = m1[o10] * (1.0f - wx) + m1[o11] * wx;
        float v1 = t1 * (1.0f - wy) + u1 * wy;

        float t2 = m2[o00] * (1.0f - wx) + m2[o01] * wx;
        float u2 = m2[o10] * (1.0f - wx) + m2[o11] * wx;
        float v2 = t2 * (1.0f - wy) + u2 * wy;

        float w = fmaf(v0, v0, fmaf(v1, v1, v2 * v2));

        // Scatter into pair layout.
        int jp   = i >> 1;
        int lane = i & 1;
        float* fa = (float*)sa;
        float* fb = (float*)sb;
        fa[4 * jp + lane]     = v0;
        fa[4 * jp + 2 + lane] = v1;
        fb[4 * jp + lane]     = v2;
        fb[4 * jp + 2 + lane] = w;
    }
    __syncthreads();

    // --- Load this thread's pc points; duplicate coords into packed regs ---
    const float* __restrict__ px = pc + (b * 3 + 0) * M_;
    const float* __restrict__ py = pc + (b * 3 + 1) * M_;
    const float* __restrict__ pz = pc + (b * 3 + 2) * M_;

    const int q0 = chunk * (THREADS_ * RPT_) + threadIdx.x;   // pc point index

    unsigned long long ax2[RPT_], ay2[RPT_], az2[RPT_];
    float b0[RPT_], b1[RPT_];
#pragma unroll
    for (int r = 0; r < RPT_; r++) {
        int q = q0 + r * THREADS_;
        float x = px[q], y = py[q], z = pz[q];
        ax2[r] = pack2(-2.0f * x, -2.0f * x);
        ay2[r] = pack2(-2.0f * y, -2.0f * y);
        az2[r] = pack2(-2.0f * z, -2.0f * z);
        b0[r] = FLT_MAX;
        b1[r] = FLT_MAX;
    }

    // --- Hot loop over mesh PAIRS: one packed FMA chain = 2 mesh distances ---
    const int pairs = cnt >> 1;
#pragma unroll 2
    for (int jp = 0; jp < pairs; jp++) {
        ulonglong2 A  = sa[jp];   // broadcast LDS.128: {x0,x1},{y0,y1}
        ulonglong2 Bv = sb[jp];   // {z0,z1},{w0,w1}
#pragma unroll
        for (int r = 0; r < RPT_; r++) {
            df2 t;
            t.u = fma2(A.x, ax2[r], fma2(A.y, ay2[r], fma2(Bv.x, az2[r], Bv.y)));
            b0[r] = fminf(b0[r], t.f.x);
            b1[r] = fminf(b1[r], t.f.y);
        }
    }

    // --- Epilogue: cross-lane min, |p|^2, then order-independent atomic min
    //     (exact: min has no rounding; key is monotonic) ---
#pragma unroll
    for (int r = 0; r < RPT_; r++) {
        int q = q0 + r * THREADS_;
        float x = px[q], y = py[q], z = pz[q];
        float pp = fmaf(x, x, fmaf(y, y, z * z));
        float d  = fminf(b0[r], b1[r]) + pp;
        atomicMax(&g_best[b * M_ + q], ~enc_f32(d));   // 0 == +inf sentinel
    }
}

// ---------------------------------------------------------------------------
// Kernel 2: read g_best (1 value/thread), reset it to 0 for the next replay,
// block tree-sum; last block (atomic ticket) sums 64 partials in fixed order
// and writes the mean. Fully deterministic.
// ---------------------------------------------------------------------------
__global__ __launch_bounds__(THREADS_)
void reduce_kernel(float* __restrict__ out) {
    __shared__ float red[THREADS_];
    __shared__ unsigned int s_ticket;

    const int i = blockIdx.x * THREADS_ + threadIdx.x;   // i < 16384
    float v = dec_f32(~g_best[i]);
    g_best[i] = 0u;                                      // re-arm for next replay
    red[threadIdx.x] = v;
    __syncthreads();
#pragma unroll
    for (int off = THREADS_ / 2; off > 0; off >>= 1) {
        if (threadIdx.x < off) red[threadIdx.x] += red[threadIdx.x + off];
        __syncthreads();
    }
    if (threadIdx.x == 0) {
        g_sums[blockIdx.x] = red[0];
        __threadfence();
        s_ticket = atomicAdd(&g_ticket, 1u);
    }
    __syncthreads();

    if (s_ticket == RBLOCKS_ - 1) {          // last block to finish
        if (threadIdx.x < RBLOCKS_) red[threadIdx.x] = g_sums[threadIdx.x];
        __syncthreads();
#pragma unroll
        for (int off = RBLOCKS_ / 2; off > 0; off >>= 1) {
            if (threadIdx.x < off) red[threadIdx.x] += red[threadIdx.x + off];
            __syncthreads();
        }
        if (threadIdx.x == 0) {
            out[0] = red[0] / (float)(B_ * M_);
            g_ticket = 0;                     // reset for next graph replay
        }
    }
}

// ---------------------------------------------------------------------------
extern "C" void kernel_launch(void* const* d_in, const int* in_sizes, int n_in,
                              void* d_out, int out_size) {
    const float* mesh = (const float*)d_in[0];
    const float* pc   = (const float*)d_in[1];
    float* out = (float*)d_out;

    dim3 grid(B_, CHUNKS_, SLICES_);
    dist_kernel<<<grid, THREADS_>>>(mesh, pc);
    reduce_kernel<<<RBLOCKS_, THREADS_>>>(out);
}